// round 7
// baseline (speedup 1.0000x reference)
#include <cuda_runtime.h>
#include <cuda_bf16.h>
#include <cstdint>

// ---------------- problem constants ----------------
#define Nn   100000
#define Ee   600000
#define Gg   64
#define FIN  32
#define Wd   128
#define EPSv 1e-5f

// ---------------- device scratch (static, no allocs) ----------------
__device__ float g_h[(size_t)Nn * Wd];     // 51.2 MB
__device__ float g_a[(size_t)Nn * Wd];     // 51.2 MB
__device__ float g_dinv[Nn];
__device__ int   g_deg[Nn];
__device__ float g_stats[2 * Wd];
__device__ float g_pool[Gg * Wd];
// pre-split weights (W2,W3,W4) as B[n][k] hi/lo bf16 (plain row-major)
__device__ __nv_bfloat16 g_Bhi[3 * Wd * Wd];
__device__ __nv_bfloat16 g_Blo[3 * Wd * Wd];

// ---------------- helpers ----------------
__device__ __forceinline__ uint32_t smem_u32(const void* p) {
    uint32_t a;
    asm("{ .reg .u64 t; cvta.to.shared.u64 t, %1; cvt.u32.u64 %0, t; }" : "=r"(a) : "l"(p));
    return a;
}

// ---------------- zero / degree / normalization ----------------
__global__ void k_zero_misc() {
    int i = blockIdx.x * blockDim.x + threadIdx.x;
    if (i < Nn) g_deg[i] = 0;
    if (i < 2 * Wd) g_stats[i] = 0.f;
    if (i < Gg * Wd) g_pool[i] = 0.f;
}

__global__ void k_deg(const int* __restrict__ dst) {
    int e = blockIdx.x * blockDim.x + threadIdx.x;
    if (e < Ee) atomicAdd(&g_deg[dst[e]], 1);
}

__global__ void k_dinv() {
    int i = blockIdx.x * blockDim.x + threadIdx.x;
    if (i < Nn) g_dinv[i] = rsqrtf((float)g_deg[i] + 1.0f);
}

// ---------------- weight split: W[k][n] -> B[n][k] hi/lo bf16 ----------------
__global__ void k_wsplit(const float* __restrict__ W2, const float* __restrict__ W3,
                         const float* __restrict__ W4) {
    int i = blockIdx.x * blockDim.x + threadIdx.x;
    if (i >= 3 * Wd * Wd) return;
    int m = i / (Wd * Wd);
    int idx = i - m * (Wd * Wd);
    int k = idx >> 7;
    int n = idx & 127;
    const float* Wm = (m == 0) ? W2 : (m == 1) ? W3 : W4;
    float w = Wm[k * Wd + n];
    __nv_bfloat16 h = __float2bfloat16(w);
    __nv_bfloat16 l = __float2bfloat16(w - __bfloat162float(h));
    g_Bhi[m * Wd * Wd + n * Wd + k] = h;
    g_Blo[m * Wd * Wd + n * Wd + k] = l;
}

// ---------------- edge scatter ----------------
__global__ void k_scatter(const int* __restrict__ src, const int* __restrict__ dst) {
    int idx  = blockIdx.x * blockDim.x + threadIdx.x;
    int e    = idx >> 5;
    int lane = idx & 31;
    if (e >= Ee) return;
    int s = src[e], d = dst[e];
    float w = g_dinv[s] * g_dinv[d];
    float4 v = *(const float4*)&g_h[(size_t)s * Wd + lane * 4];
    float* ap = &g_a[(size_t)d * Wd + lane * 4];
    asm volatile("red.relaxed.gpu.global.add.v4.f32 [%0], {%1, %2, %3, %4};"
                 :: "l"(ap), "f"(v.x * w), "f"(v.y * w), "f"(v.z * w), "f"(v.w * w)
                 : "memory");
}

// ---------------- fp32 SGEMM (conv1 only, K=32) ----------------
enum { LOAD_NONE = 0, LOAD_RELU = 1, LOAD_BN = 2 };

template <int LOADM, bool BIAS, bool RELU, bool SELF>
__global__ __launch_bounds__(256, 2) void k_gemm(const float* __restrict__ A,
                                                 const float* __restrict__ Bm,
                                                 const float* __restrict__ bias,
                                                 float* __restrict__ C, int K) {
    __shared__ float As[2][16][132];
    __shared__ float Bs[2][16][128];

    int tid = threadIdx.x;
    int rb  = blockIdx.x * 128;
    int tx  = tid & 15;
    int ty  = tid >> 4;
    int lr  = tid >> 2;
    int kq  = (tid & 3) * 4;
    int bk  = tid >> 4;
    int bc  = (tid & 15) * 8;

    float4 pa[2], pb[2];

    auto ldTile = [&](int kc) {
#pragma unroll
        for (int h = 0; h < 2; h++) {
            int r = rb + lr + h * 64;
            float4 v = make_float4(0.f, 0.f, 0.f, 0.f);
            if (r < Nn) v = *(const float4*)&A[(size_t)r * K + kc * 16 + kq];
            pa[h] = v;
        }
        const float* bp = &Bm[(size_t)(kc * 16 + bk) * Wd + bc];
        pb[0] = *(const float4*)bp;
        pb[1] = *(const float4*)(bp + 4);
    };

    auto stTile = [&](int buf) {
#pragma unroll
        for (int h = 0; h < 2; h++) {
            float4 v = pa[h];
            As[buf][kq + 0][lr + h * 64] = v.x;
            As[buf][kq + 1][lr + h * 64] = v.y;
            As[buf][kq + 2][lr + h * 64] = v.z;
            As[buf][kq + 3][lr + h * 64] = v.w;
        }
        *(float4*)&Bs[buf][bk][bc]     = pb[0];
        *(float4*)&Bs[buf][bk][bc + 4] = pb[1];
    };

    unsigned long long acc[8][4];
#pragma unroll
    for (int i = 0; i < 8; i++)
#pragma unroll
        for (int j = 0; j < 4; j++) acc[i][j] = 0ull;

    int nk = K >> 4;
    ldTile(0);
    stTile(0);
    __syncthreads();

    for (int kc = 0; kc < nk; kc++) {
        if (kc + 1 < nk) ldTile(kc + 1);
        int buf = kc & 1;
#pragma unroll
        for (int k = 0; k < 16; k++) {
            float4 a0 = *(const float4*)&As[buf][k][ty * 8];
            float4 a1 = *(const float4*)&As[buf][k][ty * 8 + 4];
            ulonglong2 b0 = *(const ulonglong2*)&Bs[buf][k][tx * 8];
            ulonglong2 b1 = *(const ulonglong2*)&Bs[buf][k][tx * 8 + 4];
            unsigned long long bb[4] = {b0.x, b0.y, b1.x, b1.y};
            float av[8] = {a0.x, a0.y, a0.z, a0.w, a1.x, a1.y, a1.z, a1.w};
#pragma unroll
            for (int i = 0; i < 8; i++) {
                unsigned long long ad;
                unsigned int ai = __float_as_uint(av[i]);
                asm("mov.b64 %0, {%1, %1};" : "=l"(ad) : "r"(ai));
#pragma unroll
                for (int j = 0; j < 4; j++)
                    asm("fma.rn.f32x2 %0, %1, %2, %0;"
                        : "+l"(acc[i][j]) : "l"(ad), "l"(bb[j]));
            }
        }
        if (kc + 1 < nk) {
            stTile((kc + 1) & 1);
            __syncthreads();
        }
    }

#pragma unroll
    for (int i = 0; i < 8; i++) {
        int r = rb + ty * 8 + i;
        if (r < Nn) {
            float out[8];
#pragma unroll
            for (int j = 0; j < 4; j++) {
                union { unsigned long long u; float2 f; } t;
                t.u = acc[i][j];
                out[2 * j]     = t.f.x;
                out[2 * j + 1] = t.f.y;
            }
            float os[8];
#pragma unroll
            for (int j = 0; j < 8; j++) {
                float v = out[j];
                if (BIAS) v += bias[tx * 8 + j];
                if (RELU) v = fmaxf(v, 0.f);
                os[j] = v;
            }
            float* cp = &C[(size_t)r * Wd + tx * 8];
            *(float4*)(cp)     = make_float4(os[0], os[1], os[2], os[3]);
            *(float4*)(cp + 4) = make_float4(os[4], os[5], os[6], os[7]);
            if (SELF) {
                float dv = g_dinv[r];
                float ds = dv * dv;
                float* ap = &g_a[(size_t)r * Wd + tx * 8];
                float4 s0, s1;
                s0.x = fmaf(out[0], ds, bias[tx * 8 + 0]);
                s0.y = fmaf(out[1], ds, bias[tx * 8 + 1]);
                s0.z = fmaf(out[2], ds, bias[tx * 8 + 2]);
                s0.w = fmaf(out[3], ds, bias[tx * 8 + 3]);
                s1.x = fmaf(out[4], ds, bias[tx * 8 + 4]);
                s1.y = fmaf(out[5], ds, bias[tx * 8 + 5]);
                s1.z = fmaf(out[6], ds, bias[tx * 8 + 6]);
                s1.w = fmaf(out[7], ds, bias[tx * 8 + 7]);
                *(float4*)(ap)     = s0;
                *(float4*)(ap + 4) = s1;
            }
        }
    }
}

// ---------------- bf16x3 mma.sync GEMM (K=128, N=128) ----------------
// smem: Ahi, Alo, Bhi, Blo as [128 rows][136 bf16] (row = 272B; 272%128=16 ->
// ldmatrix 8-row phases cover banks 0,16,...,112 conflict-free).
#define MG_STRIDE 136
#define MG_ROWB   (MG_STRIDE * 2)
#define MG_TILEB  (128 * MG_ROWB)          // 34816 B
#define MG_AHI 0
#define MG_ALO MG_TILEB
#define MG_BHI (2 * MG_TILEB)
#define MG_BLO (3 * MG_TILEB)
#define MG_SMEM (4 * MG_TILEB)             // 139264 B

#define LDSM_X4(r0, r1, r2, r3, a) \
    asm volatile("ldmatrix.sync.aligned.m8n8.x4.shared.b16 {%0,%1,%2,%3}, [%4];" \
        : "=r"(r0), "=r"(r1), "=r"(r2), "=r"(r3) : "r"(a))
#define LDSM_X2(r0, r1, a) \
    asm volatile("ldmatrix.sync.aligned.m8n8.x2.shared.b16 {%0,%1}, [%2];" \
        : "=r"(r0), "=r"(r1) : "r"(a))
#define MMA16816(d, a, b) \
    asm volatile("mma.sync.aligned.m16n8k16.row.col.f32.bf16.bf16.f32 " \
        "{%0,%1,%2,%3}, {%4,%5,%6,%7}, {%8,%9}, {%0,%1,%2,%3};" \
        : "+f"((d)[0]), "+f"((d)[1]), "+f"((d)[2]), "+f"((d)[3]) \
        : "r"((a)[0]), "r"((a)[1]), "r"((a)[2]), "r"((a)[3]), "r"((b)[0]), "r"((b)[1]))

template <int LOADM, bool BIAS, bool RELU, bool SELF>
__global__ __launch_bounds__(256, 1) void k_mgemm(const float* __restrict__ A,
                                                  const __nv_bfloat16* __restrict__ Bh,
                                                  const __nv_bfloat16* __restrict__ Bl,
                                                  const float* __restrict__ bias,
                                                  float* __restrict__ C) {
    extern __shared__ __align__(16) char smem[];
    int tid = threadIdx.x;
    int rb  = blockIdx.x * 128;

    // ---- stage A (load + transform + hi/lo split) and B (copy) into smem ----
    for (int item = tid; item < 2048; item += 256) {
        int r  = item >> 4;          // 0..127
        int kc = item & 15;          // 8-element group
        // B copy (hi/lo), plain [n][k] -> padded rows
        {
            uint4 bh = *(const uint4*)&Bh[r * Wd + kc * 8];
            uint4 bl = *(const uint4*)&Bl[r * Wd + kc * 8];
            *(uint4*)(smem + MG_BHI + r * MG_ROWB + kc * 16) = bh;
            *(uint4*)(smem + MG_BLO + r * MG_ROWB + kc * 16) = bl;
        }
        // A
        int row = rb + r;
        float v[8];
        if (row < Nn) {
            float4 u0 = *(const float4*)&A[(size_t)row * Wd + kc * 8];
            float4 u1 = *(const float4*)&A[(size_t)row * Wd + kc * 8 + 4];
            v[0] = u0.x; v[1] = u0.y; v[2] = u0.z; v[3] = u0.w;
            v[4] = u1.x; v[5] = u1.y; v[6] = u1.z; v[7] = u1.w;
        } else {
#pragma unroll
            for (int j = 0; j < 8; j++) v[j] = 0.f;
        }
        if (LOADM == LOAD_RELU) {
#pragma unroll
            for (int j = 0; j < 8; j++) v[j] = fmaxf(v[j], 0.f);
        } else if (LOADM == LOAD_BN) {
            int c0 = kc * 8;
#pragma unroll
            for (int j = 0; j < 8; j++)
                v[j] = fmaxf(fmaf(v[j], g_stats[c0 + j], g_stats[Wd + c0 + j]), 0.f);
        }
        uint32_t hi[4], lo[4];
#pragma unroll
        for (int j = 0; j < 4; j++) {
            float a0 = v[2 * j], a1 = v[2 * j + 1];
            __nv_bfloat16 h0 = __float2bfloat16(a0), h1 = __float2bfloat16(a1);
            float r0 = a0 - __bfloat162float(h0), r1 = a1 - __bfloat162float(h1);
            __nv_bfloat16 l0 = __float2bfloat16(r0), l1 = __float2bfloat16(r1);
            unsigned short hb0, hb1, lb0, lb1;
            memcpy(&hb0, &h0, 2); memcpy(&hb1, &h1, 2);
            memcpy(&lb0, &l0, 2); memcpy(&lb1, &l1, 2);
            hi[j] = ((uint32_t)hb1 << 16) | hb0;
            lo[j] = ((uint32_t)lb1 << 16) | lb0;
        }
        *(uint4*)(smem + MG_AHI + r * MG_ROWB + kc * 16) = make_uint4(hi[0], hi[1], hi[2], hi[3]);
        *(uint4*)(smem + MG_ALO + r * MG_ROWB + kc * 16) = make_uint4(lo[0], lo[1], lo[2], lo[3]);
    }
    __syncthreads();

    // ---- mma phase ----
    int lane = tid & 31;
    int wid  = tid >> 5;
    int wm   = (wid & 3) * 32;          // warp row offset
    int wn   = (wid >> 2) * 64;         // warp col offset
    uint32_t sb = smem_u32(smem);

    // ldmatrix lane addresses
    uint32_t aAddr = sb + MG_AHI + (wm + (lane & 15)) * MG_ROWB + (lane >> 4) * 16;
    uint32_t bAddr = sb + MG_BHI + (wn + (lane & 7)) * MG_ROWB + ((lane >> 3) & 1) * 16;

    float acc[2][8][4];
#pragma unroll
    for (int mt = 0; mt < 2; mt++)
#pragma unroll
        for (int nt = 0; nt < 8; nt++)
#pragma unroll
            for (int e = 0; e < 4; e++) acc[mt][nt][e] = 0.f;

#pragma unroll
    for (int ks = 0; ks < 8; ks++) {
        uint32_t ah[2][4], bh[8][2];
#pragma unroll
        for (int mt = 0; mt < 2; mt++)
            LDSM_X4(ah[mt][0], ah[mt][1], ah[mt][2], ah[mt][3],
                    aAddr + mt * 16 * MG_ROWB + ks * 32);
#pragma unroll
        for (int nt = 0; nt < 8; nt++)
            LDSM_X2(bh[nt][0], bh[nt][1], bAddr + nt * 8 * MG_ROWB + ks * 32);
        // hi * hi
#pragma unroll
        for (int mt = 0; mt < 2; mt++)
#pragma unroll
            for (int nt = 0; nt < 8; nt++)
                MMA16816(acc[mt][nt], ah[mt], bh[nt]);
        // hi * lo
        {
            uint32_t bl[8][2];
#pragma unroll
            for (int nt = 0; nt < 8; nt++)
                LDSM_X2(bl[nt][0], bl[nt][1],
                        bAddr + (MG_BLO - MG_BHI) + nt * 8 * MG_ROWB + ks * 32);
#pragma unroll
            for (int mt = 0; mt < 2; mt++)
#pragma unroll
                for (int nt = 0; nt < 8; nt++)
                    MMA16816(acc[mt][nt], ah[mt], bl[nt]);
        }
        // lo * hi
        {
            uint32_t al[2][4];
#pragma unroll
            for (int mt = 0; mt < 2; mt++)
                LDSM_X4(al[mt][0], al[mt][1], al[mt][2], al[mt][3],
                        aAddr + (MG_ALO - MG_AHI) + mt * 16 * MG_ROWB + ks * 32);
#pragma unroll
            for (int mt = 0; mt < 2; mt++)
#pragma unroll
                for (int nt = 0; nt < 8; nt++)
                    MMA16816(acc[mt][nt], al[mt], bh[nt]);
        }
    }

    // ---- epilogue ----
    int g = lane >> 2;
    int c = (lane & 3) * 2;
#pragma unroll
    for (int mt = 0; mt < 2; mt++) {
#pragma unroll
        for (int half = 0; half < 2; half++) {
            int row = rb + wm + mt * 16 + g + half * 8;
            if (row >= Nn) continue;
            float dsq = 0.f;
            if (SELF) { float dv = g_dinv[row]; dsq = dv * dv; }
#pragma unroll
            for (int nt = 0; nt < 8; nt++) {
                int col = wn + nt * 8 + c;
                float r0 = acc[mt][nt][half * 2 + 0];
                float r1 = acc[mt][nt][half * 2 + 1];
                float o0 = r0, o1 = r1;
                if (BIAS) { o0 += bias[col]; o1 += bias[col + 1]; }
                if (RELU) { o0 = fmaxf(o0, 0.f); o1 = fmaxf(o1, 0.f); }
                *(float2*)&C[(size_t)row * Wd + col] = make_float2(o0, o1);
                if (SELF) {
                    float s0 = fmaf(r0, dsq, bias[col]);
                    float s1 = fmaf(r1, dsq, bias[col + 1]);
                    *(float2*)&g_a[(size_t)row * Wd + col] = make_float2(s0, s1);
                }
            }
        }
    }
}

// ---------------- BN stats over g_h ----------------
__global__ void k_bnstats() {
    int c = threadIdx.x;   // 128
    float s = 0.f, q = 0.f;
    for (int r = blockIdx.x; r < Nn; r += gridDim.x) {
        float v = g_h[(size_t)r * Wd + c];
        s += v;
        q += v * v;
    }
    atomicAdd(&g_stats[c], s);
    atomicAdd(&g_stats[Wd + c], q);
}

__global__ void k_bnfin(const float* __restrict__ gamma, const float* __restrict__ beta) {
    int c = threadIdx.x;  // 128
    float mu  = g_stats[c] * (1.f / Nn);
    float var = g_stats[Wd + c] * (1.f / Nn) - mu * mu;
    float rs  = rsqrtf(var + EPSv);
    float sc  = gamma[c] * rs;
    g_stats[c]      = sc;
    g_stats[Wd + c] = beta[c] - mu * sc;
}

// ---------------- per-graph max pool ----------------
#define POOL_ROWS 500
__global__ void k_segmax(const int* __restrict__ batch) {
    int c  = threadIdx.x;
    int r0 = blockIdx.x * POOL_ROWS;
    int r1 = r0 + POOL_ROWS;
    int cur = batch[r0];
    float m = g_a[(size_t)r0 * Wd + c];
    for (int r = r0 + 1; r < r1; r++) {
        int gID = batch[r];
        float v = g_a[(size_t)r * Wd + c];
        if (gID != cur) {
            atomicMax((int*)&g_pool[cur * Wd + c], __float_as_int(m));
            cur = gID;
            m = v;
        } else {
            m = fmaxf(m, v);
        }
    }
    atomicMax((int*)&g_pool[cur * Wd + c], __float_as_int(m));
}

// ---------------- head MLP ----------------
__global__ void k_final(const float* __restrict__ W5, const float* __restrict__ b5,
                        const float* __restrict__ g2, const float* __restrict__ be2,
                        const float* __restrict__ W6, const float* __restrict__ b6,
                        float* __restrict__ out) {
    __shared__ float S[64][65];
    __shared__ float sc[64], tc[64];
    int tid = threadIdx.x;
    for (int idx = tid; idx < 64 * 64; idx += 256) {
        int r = idx >> 6, c = idx & 63;
        float acc = b5[c];
        for (int k = 0; k < 128; k++) acc = fmaf(g_pool[r * 128 + k], W5[k * 64 + c], acc);
        S[r][c] = acc;
    }
    __syncthreads();
    if (tid < 64) {
        int c = tid;
        float s = 0.f, q = 0.f;
        for (int r = 0; r < 64; r++) { float v = S[r][c]; s += v; q += v * v; }
        float mu  = s * (1.f / 64);
        float var = q * (1.f / 64) - mu * mu;
        float rs  = rsqrtf(var + EPSv);
        float s_  = g2[c] * rs;
        sc[c] = s_;
        tc[c] = be2[c] - mu * s_;
    }
    __syncthreads();
    if (tid < 64) {
        int r = tid;
        float o = b6[0];
        for (int c = 0; c < 64; c++) {
            float v = fmaxf(fmaf(S[r][c], sc[c], tc[c]), 0.f);
            o = fmaf(v, W6[c], o);
        }
        out[r] = o;
    }
}

// ---------------- launch ----------------
extern "C" void kernel_launch(void* const* d_in, const int* in_sizes, int n_in,
                              void* d_out, int out_size) {
    const float* x    = (const float*)d_in[0];
    const int*   ei   = (const int*)d_in[1];
    const int*   src  = ei;
    const int*   dst  = ei + Ee;
    const int*   batch= (const int*)d_in[2];
    const float* W1 = (const float*)d_in[3];
    const float* b1 = (const float*)d_in[4];
    const float* W2 = (const float*)d_in[5];
    const float* b2 = (const float*)d_in[6];
    const float* W3 = (const float*)d_in[7];
    const float* b3 = (const float*)d_in[8];
    const float* g1 = (const float*)d_in[9];
    const float* be1= (const float*)d_in[10];
    const float* W4 = (const float*)d_in[11];
    const float* b4 = (const float*)d_in[12];
    const float* W5 = (const float*)d_in[13];
    const float* b5 = (const float*)d_in[14];
    const float* g2 = (const float*)d_in[15];
    const float* be2= (const float*)d_in[16];
    const float* W6 = (const float*)d_in[17];
    const float* b6 = (const float*)d_in[18];
    float* out = (float*)d_out;

    float *h_ptr = nullptr, *a_ptr = nullptr;
    __nv_bfloat16 *bhi = nullptr, *blo = nullptr;
    cudaGetSymbolAddress((void**)&h_ptr, g_h);
    cudaGetSymbolAddress((void**)&a_ptr, g_a);
    cudaGetSymbolAddress((void**)&bhi, g_Bhi);
    cudaGetSymbolAddress((void**)&blo, g_Blo);

    cudaFuncSetAttribute(k_mgemm<LOAD_RELU, false, false, true>,
                         cudaFuncAttributeMaxDynamicSharedMemorySize, MG_SMEM);
    cudaFuncSetAttribute(k_mgemm<LOAD_RELU, true, false, false>,
                         cudaFuncAttributeMaxDynamicSharedMemorySize, MG_SMEM);
    cudaFuncSetAttribute(k_mgemm<LOAD_BN, true, true, false>,
                         cudaFuncAttributeMaxDynamicSharedMemorySize, MG_SMEM);

    const int TB = 256;
    int gridN    = (Nn + TB - 1) / TB;
    int gridE    = (Ee + TB - 1) / TB;
    int gridScat = ((Ee * 32) + TB - 1) / TB;
    int gridT    = (Nn + 127) / 128;

    k_zero_misc<<<gridN, TB>>>();
    k_wsplit<<<(3 * Wd * Wd + TB - 1) / TB, TB>>>(W2, W3, W4);
    k_deg<<<gridE, TB>>>(dst);
    k_dinv<<<gridN, TB>>>();

    // conv1 (fp32, K=32): g_h = x@W1 ; g_a = g_h*dinv^2 + b1 ; scatter
    k_gemm<LOAD_NONE, false, false, true><<<gridT, TB>>>(x, W1, b1, h_ptr, FIN);
    k_scatter<<<gridScat, TB>>>(src, dst);

    // conv2 (mma bf16x3): g_h = relu(g_a)@W2 ; g_a = g_h*dinv^2 + b2 ; scatter
    k_mgemm<LOAD_RELU, false, false, true><<<gridT, TB, MG_SMEM>>>(a_ptr, bhi, blo, b2, h_ptr);
    k_scatter<<<gridScat, TB>>>(src, dst);

    // mlp_first: g_h = relu(g_a)@W3 + b3 ; BN ; g_a = relu(bn(g_h)@W4 + b4)
    k_mgemm<LOAD_RELU, true, false, false><<<gridT, TB, MG_SMEM>>>(a_ptr, bhi + Wd * Wd, blo + Wd * Wd, b3, h_ptr);
    k_bnstats<<<256, 128>>>();
    k_bnfin<<<1, 128>>>(g1, be1);
    k_mgemm<LOAD_BN, true, true, false><<<gridT, TB, MG_SMEM>>>(h_ptr, bhi + 2 * Wd * Wd, blo + 2 * Wd * Wd, b4, a_ptr);

    // global max pool + head
    k_segmax<<<Nn / POOL_ROWS, 128>>>(batch);
    k_final<<<1, 256>>>(W5, b5, g2, be2, W6, b6, out);
}

// round 8
// speedup vs baseline: 1.1655x; 1.1655x over previous
#include <cuda_runtime.h>
#include <cstdint>

// ---------------- problem constants ----------------
#define Nn   100000
#define Ee   600000
#define Gg   64
#define FIN  32
#define Wd   128
#define EPSv 1e-5f

// ---------------- device scratch (static, no allocs) ----------------
__device__ float g_h[(size_t)Nn * Wd];     // 51.2 MB
__device__ float g_a[(size_t)Nn * Wd];     // 51.2 MB
__device__ float g_dinv[Nn];
__device__ int   g_deg[Nn];
__device__ float g_stats[2 * Wd];
__device__ float g_pool[Gg * Wd];
// CSR (edges grouped by dst)
__device__ int   g_rowptr[Nn + 1];
__device__ int   g_cursor[Nn];
__device__ int   g_esrc[Ee];
__device__ int   g_blk[512];               // block sums for scan (391 used)

#define SCAN_BLOCKS 391

// ---------------- zero / degree / normalization ----------------
__global__ void k_zero_misc() {
    int i = blockIdx.x * blockDim.x + threadIdx.x;
    if (i < Nn) { g_deg[i] = 0; g_cursor[i] = 0; }
    if (i < 2 * Wd) g_stats[i] = 0.f;
    if (i < Gg * Wd) g_pool[i] = 0.f;
}

__global__ void k_deg(const int* __restrict__ dst) {
    int e = blockIdx.x * blockDim.x + threadIdx.x;
    if (e < Ee) atomicAdd(&g_deg[dst[e]], 1);
}

__global__ void k_dinv() {
    int i = blockIdx.x * blockDim.x + threadIdx.x;
    if (i < Nn) g_dinv[i] = rsqrtf((float)g_deg[i] + 1.0f);
}

// ---------------- CSR build: scan of degrees ----------------
__global__ void k_scan1() {            // block sums
    __shared__ int sh[256];
    int i = blockIdx.x * 256 + threadIdx.x;
    sh[threadIdx.x] = (i < Nn) ? g_deg[i] : 0;
    __syncthreads();
    for (int s = 128; s > 0; s >>= 1) {
        if (threadIdx.x < s) sh[threadIdx.x] += sh[threadIdx.x + s];
        __syncthreads();
    }
    if (threadIdx.x == 0) g_blk[blockIdx.x] = sh[0];
}

__global__ void k_scan2() {            // exclusive scan of block sums (1 block, 512 thr)
    __shared__ int sh[512];
    int t = threadIdx.x;
    sh[t] = (t < SCAN_BLOCKS) ? g_blk[t] : 0;
    __syncthreads();
    int val = sh[t];
    for (int off = 1; off < 512; off <<= 1) {
        int v = (t >= off) ? sh[t - off] : 0;
        __syncthreads();
        sh[t] += v;
        __syncthreads();
    }
    if (t < SCAN_BLOCKS) g_blk[t] = sh[t] - val;   // exclusive
    if (t == 0) g_rowptr[Nn] = Ee;
}

__global__ void k_scan3() {            // per-block exclusive scan + offset -> rowptr
    __shared__ int sh[256];
    int i = blockIdx.x * 256 + threadIdx.x;
    int t = threadIdx.x;
    int val = (i < Nn) ? g_deg[i] : 0;
    sh[t] = val;
    __syncthreads();
    for (int off = 1; off < 256; off <<= 1) {
        int v = (t >= off) ? sh[t - off] : 0;
        __syncthreads();
        sh[t] += v;
        __syncthreads();
    }
    if (i < Nn) g_rowptr[i] = g_blk[blockIdx.x] + sh[t] - val;
}

__global__ void k_fill(const int* __restrict__ src, const int* __restrict__ dst) {
    int e = blockIdx.x * blockDim.x + threadIdx.x;
    if (e >= Ee) return;
    int d = dst[e];
    int pos = g_rowptr[d] + atomicAdd(&g_cursor[d], 1);
    g_esrc[pos] = src[e];
}

// ---------------- CSR gather: g_a[n] += sum_e h[src_e]*dinv[src_e]*dinv[n] ----------------
// one warp per node, 4 feats per lane; g_a holds the self-loop base already.
__global__ void k_gather() {
    int n = blockIdx.x * 8 + (threadIdx.x >> 5);
    if (n >= Nn) return;
    int lane = threadIdx.x & 31;
    int beg = g_rowptr[n], end = g_rowptr[n + 1];
    float dn = g_dinv[n];
    float4 acc = *(const float4*)&g_a[(size_t)n * Wd + lane * 4];
    for (int e = beg; e < end; e++) {
        int s = g_esrc[e];
        float w = g_dinv[s] * dn;
        float4 v = *(const float4*)&g_h[(size_t)s * Wd + lane * 4];
        acc.x = fmaf(v.x, w, acc.x);
        acc.y = fmaf(v.y, w, acc.y);
        acc.z = fmaf(v.z, w, acc.z);
        acc.w = fmaf(v.w, w, acc.w);
    }
    *(float4*)&g_a[(size_t)n * Wd + lane * 4] = acc;
}

// ---------------- fused fp32 SGEMM (f32x2 packed), 128x128 tile ----------------
enum { LOAD_NONE = 0, LOAD_RELU = 1, LOAD_BN = 2 };

template <int LOADM, bool BIAS, bool RELU, bool SELF, bool STATS>
__global__ __launch_bounds__(256, 2) void k_gemm(const float* __restrict__ A,
                                                 const float* __restrict__ Bm,
                                                 const float* __restrict__ bias,
                                                 float* __restrict__ C, int K) {
    __shared__ float As[2][16][132];
    __shared__ float Bs[2][16][128];
    __shared__ float s_st[2][128];

    int tid = threadIdx.x;
    int rb  = blockIdx.x * 128;
    int tx  = tid & 15;
    int ty  = tid >> 4;
    int lr  = tid >> 2;
    int kq  = (tid & 3) * 4;
    int bk  = tid >> 4;
    int bc  = (tid & 15) * 8;

    float4 pa[2], pb[2];

    auto ldTile = [&](int kc) {
#pragma unroll
        for (int h = 0; h < 2; h++) {
            int r = rb + lr + h * 64;
            float4 v = make_float4(0.f, 0.f, 0.f, 0.f);
            if (r < Nn) v = *(const float4*)&A[(size_t)r * K + kc * 16 + kq];
            pa[h] = v;
        }
        const float* bp = &Bm[(size_t)(kc * 16 + bk) * Wd + bc];
        pb[0] = *(const float4*)bp;
        pb[1] = *(const float4*)(bp + 4);
    };

    auto stTile = [&](int buf, int kc) {
#pragma unroll
        for (int h = 0; h < 2; h++) {
            float4 v = pa[h];
            if (LOADM == LOAD_RELU) {
                v.x = fmaxf(v.x, 0.f); v.y = fmaxf(v.y, 0.f);
                v.z = fmaxf(v.z, 0.f); v.w = fmaxf(v.w, 0.f);
            } else if (LOADM == LOAD_BN) {
                int c0 = kc * 16 + kq;
                v.x = fmaxf(fmaf(v.x, g_stats[c0 + 0], g_stats[Wd + c0 + 0]), 0.f);
                v.y = fmaxf(fmaf(v.y, g_stats[c0 + 1], g_stats[Wd + c0 + 1]), 0.f);
                v.z = fmaxf(fmaf(v.z, g_stats[c0 + 2], g_stats[Wd + c0 + 2]), 0.f);
                v.w = fmaxf(fmaf(v.w, g_stats[c0 + 3], g_stats[Wd + c0 + 3]), 0.f);
            }
            As[buf][kq + 0][lr + h * 64] = v.x;
            As[buf][kq + 1][lr + h * 64] = v.y;
            As[buf][kq + 2][lr + h * 64] = v.z;
            As[buf][kq + 3][lr + h * 64] = v.w;
        }
        *(float4*)&Bs[buf][bk][bc]     = pb[0];
        *(float4*)&Bs[buf][bk][bc + 4] = pb[1];
    };

    unsigned long long acc[8][4];
#pragma unroll
    for (int i = 0; i < 8; i++)
#pragma unroll
        for (int j = 0; j < 4; j++) acc[i][j] = 0ull;

    int nk = K >> 4;
    ldTile(0);
    stTile(0, 0);
    __syncthreads();

    for (int kc = 0; kc < nk; kc++) {
        if (kc + 1 < nk) ldTile(kc + 1);
        int buf = kc & 1;
#pragma unroll
        for (int k = 0; k < 16; k++) {
            float4 a0 = *(const float4*)&As[buf][k][ty * 8];
            float4 a1 = *(const float4*)&As[buf][k][ty * 8 + 4];
            ulonglong2 b0 = *(const ulonglong2*)&Bs[buf][k][tx * 8];
            ulonglong2 b1 = *(const ulonglong2*)&Bs[buf][k][tx * 8 + 4];
            unsigned long long bb[4] = {b0.x, b0.y, b1.x, b1.y};
            float av[8] = {a0.x, a0.y, a0.z, a0.w, a1.x, a1.y, a1.z, a1.w};
#pragma unroll
            for (int i = 0; i < 8; i++) {
                unsigned long long ad;
                unsigned int ai = __float_as_uint(av[i]);
                asm("mov.b64 %0, {%1, %1};" : "=l"(ad) : "r"(ai));
#pragma unroll
                for (int j = 0; j < 4; j++)
                    asm("fma.rn.f32x2 %0, %1, %2, %0;"
                        : "+l"(acc[i][j]) : "l"(ad), "l"(bb[j]));
            }
        }
        if (kc + 1 < nk) {
            stTile((kc + 1) & 1, kc + 1);
            __syncthreads();
        }
    }

    // ---------------- epilogue ----------------
    if (STATS) {
        s_st[tid >> 7][tid & 127] = 0.f;
        __syncthreads();
    }

    float cs[8], cq[8];
    if (STATS) {
#pragma unroll
        for (int j = 0; j < 8; j++) { cs[j] = 0.f; cq[j] = 0.f; }
    }

#pragma unroll
    for (int i = 0; i < 8; i++) {
        int r = rb + ty * 8 + i;
        if (r < Nn) {
            float out[8];
#pragma unroll
            for (int j = 0; j < 4; j++) {
                union { unsigned long long u; float2 f; } t;
                t.u = acc[i][j];
                out[2 * j]     = t.f.x;
                out[2 * j + 1] = t.f.y;
            }
            float os[8];
#pragma unroll
            for (int j = 0; j < 8; j++) {
                float v = out[j];
                if (BIAS) v += bias[tx * 8 + j];
                if (RELU) v = fmaxf(v, 0.f);
                os[j] = v;
                if (STATS) { cs[j] += v; cq[j] += v * v; }
            }
            float* cp = &C[(size_t)r * Wd + tx * 8];
            *(float4*)(cp)     = make_float4(os[0], os[1], os[2], os[3]);
            *(float4*)(cp + 4) = make_float4(os[4], os[5], os[6], os[7]);
            if (SELF) {
                float dv = g_dinv[r];
                float ds = dv * dv;
                float* ap = &g_a[(size_t)r * Wd + tx * 8];
                float4 s0, s1;
                s0.x = fmaf(out[0], ds, bias[tx * 8 + 0]);
                s0.y = fmaf(out[1], ds, bias[tx * 8 + 1]);
                s0.z = fmaf(out[2], ds, bias[tx * 8 + 2]);
                s0.w = fmaf(out[3], ds, bias[tx * 8 + 3]);
                s1.x = fmaf(out[4], ds, bias[tx * 8 + 4]);
                s1.y = fmaf(out[5], ds, bias[tx * 8 + 5]);
                s1.z = fmaf(out[6], ds, bias[tx * 8 + 6]);
                s1.w = fmaf(out[7], ds, bias[tx * 8 + 7]);
                *(float4*)(ap)     = s0;
                *(float4*)(ap + 4) = s1;
            }
        }
    }

    if (STATS) {
#pragma unroll
        for (int j = 0; j < 8; j++) {
            atomicAdd(&s_st[0][tx * 8 + j], cs[j]);
            atomicAdd(&s_st[1][tx * 8 + j], cq[j]);
        }
        __syncthreads();
        if (tid < 128) {
            atomicAdd(&g_stats[tid],      s_st[0][tid]);
            atomicAdd(&g_stats[Wd + tid], s_st[1][tid]);
        }
    }
}

// ---------------- BN finalize ----------------
__global__ void k_bnfin(const float* __restrict__ gamma, const float* __restrict__ beta) {
    int c = threadIdx.x;  // 128
    float mu  = g_stats[c] * (1.f / Nn);
    float var = g_stats[Wd + c] * (1.f / Nn) - mu * mu;
    float rs  = rsqrtf(var + EPSv);
    float sc  = gamma[c] * rs;
    g_stats[c]      = sc;                // scale
    g_stats[Wd + c] = beta[c] - mu * sc; // shift
}

// ---------------- per-graph max pool (batch is sorted) ----------------
#define POOL_ROWS 500
__global__ void k_segmax(const int* __restrict__ batch) {
    int c  = threadIdx.x;
    int r0 = blockIdx.x * POOL_ROWS;
    int r1 = r0 + POOL_ROWS;
    int cur = batch[r0];
    float m = g_a[(size_t)r0 * Wd + c];
    for (int r = r0 + 1; r < r1; r++) {
        int gID = batch[r];
        float v = g_a[(size_t)r * Wd + c];
        if (gID != cur) {
            atomicMax((int*)&g_pool[cur * Wd + c], __float_as_int(m));
            cur = gID;
            m = v;
        } else {
            m = fmaxf(m, v);
        }
    }
    atomicMax((int*)&g_pool[cur * Wd + c], __float_as_int(m));
}

// ---------------- head MLP ----------------
__global__ void k_final(const float* __restrict__ W5, const float* __restrict__ b5,
                        const float* __restrict__ g2, const float* __restrict__ be2,
                        const float* __restrict__ W6, const float* __restrict__ b6,
                        float* __restrict__ out) {
    __shared__ float S[64][65];
    __shared__ float sc[64], tc[64];
    int tid = threadIdx.x;
    for (int idx = tid; idx < 64 * 64; idx += 256) {
        int r = idx >> 6, c = idx & 63;
        float acc = b5[c];
        for (int k = 0; k < 128; k++) acc = fmaf(g_pool[r * 128 + k], W5[k * 64 + c], acc);
        S[r][c] = acc;
    }
    __syncthreads();
    if (tid < 64) {
        int c = tid;
        float s = 0.f, q = 0.f;
        for (int r = 0; r < 64; r++) { float v = S[r][c]; s += v; q += v * v; }
        float mu  = s * (1.f / 64);
        float var = q * (1.f / 64) - mu * mu;
        float rs  = rsqrtf(var + EPSv);
        float s_  = g2[c] * rs;
        sc[c] = s_;
        tc[c] = be2[c] - mu * s_;
    }
    __syncthreads();
    if (tid < 64) {
        int r = tid;
        float o = b6[0];
        for (int c = 0; c < 64; c++) {
            float v = fmaxf(fmaf(S[r][c], sc[c], tc[c]), 0.f);
            o = fmaf(v, W6[c], o);
        }
        out[r] = o;
    }
}

// ---------------- launch ----------------
extern "C" void kernel_launch(void* const* d_in, const int* in_sizes, int n_in,
                              void* d_out, int out_size) {
    const float* x    = (const float*)d_in[0];
    const int*   ei   = (const int*)d_in[1];
    const int*   src  = ei;
    const int*   dst  = ei + Ee;
    const int*   batch= (const int*)d_in[2];
    const float* W1 = (const float*)d_in[3];
    const float* b1 = (const float*)d_in[4];
    const float* W2 = (const float*)d_in[5];
    const float* b2 = (const float*)d_in[6];
    const float* W3 = (const float*)d_in[7];
    const float* b3 = (const float*)d_in[8];
    const float* g1 = (const float*)d_in[9];
    const float* be1= (const float*)d_in[10];
    const float* W4 = (const float*)d_in[11];
    const float* b4 = (const float*)d_in[12];
    const float* W5 = (const float*)d_in[13];
    const float* b5 = (const float*)d_in[14];
    const float* g2 = (const float*)d_in[15];
    const float* be2= (const float*)d_in[16];
    const float* W6 = (const float*)d_in[17];
    const float* b6 = (const float*)d_in[18];
    float* out = (float*)d_out;

    float *h_ptr = nullptr, *a_ptr = nullptr;
    cudaGetSymbolAddress((void**)&h_ptr, g_h);
    cudaGetSymbolAddress((void**)&a_ptr, g_a);

    const int TB = 256;
    int gridN    = (Nn + TB - 1) / TB;        // 391
    int gridE    = (Ee + TB - 1) / TB;
    int gridGemm = (Nn + 127) / 128;
    int gridGath = (Nn + 7) / 8;              // 8 warps (nodes) per 256-thr block

    k_zero_misc<<<gridN, TB>>>();
    k_deg<<<gridE, TB>>>(dst);
    k_dinv<<<gridN, TB>>>();

    // CSR build (reused by both convs)
    k_scan1<<<SCAN_BLOCKS, 256>>>();
    k_scan2<<<1, 512>>>();
    k_scan3<<<SCAN_BLOCKS, 256>>>();
    k_fill<<<gridE, TB>>>(src, dst);

    // conv1: g_h = x@W1 ; g_a = g_h*dinv^2 + b1 ; gather adds edges
    k_gemm<LOAD_NONE, false, false, true, false><<<gridGemm, TB>>>(x, W1, b1, h_ptr, FIN);
    k_gather<<<gridGath, TB>>>();

    // conv2: A = relu(g_a) on load
    k_gemm<LOAD_RELU, false, false, true, false><<<gridGemm, TB>>>(a_ptr, W2, b2, h_ptr, Wd);
    k_gather<<<gridGath, TB>>>();

    // mlp_first: g_h = relu(g_a)@W3 + b3 (fused BN stats)
    k_gemm<LOAD_RELU, true, false, false, true><<<gridGemm, TB>>>(a_ptr, W3, b3, h_ptr, Wd);
    k_bnfin<<<1, 128>>>(g1, be1);
    // g_a = relu( relu(bn(g_h)) @ W4 + b4 )
    k_gemm<LOAD_BN, true, true, false, false><<<gridGemm, TB>>>(h_ptr, W4, b4, a_ptr, Wd);

    // global max pool + head
    k_segmax<<<Nn / POOL_ROWS, 128>>>(batch);
    k_final<<<1, 256>>>(W5, b5, g2, be2, W6, b6, out);
}